// round 5
// baseline (speedup 1.0000x reference)
#include <cuda_runtime.h>
#include <cuda_bf16.h>
#include <math.h>

// ---------------------------------------------------------------------------
// Problem constants
// ---------------------------------------------------------------------------
constexpr int B_    = 4;
constexpr int S_    = 1024;
constexpr int K_    = 1024;
constexpr int D_    = 1024;
constexpr int H_    = 16;
constexpr int HD_   = 64;
constexpr int COND_ = 1024;
constexpr int HID_  = 4096;          // MR * D
constexpr int MODD_ = 6 * D_;        // 6144
constexpr float EPS_    = 1e-5f;
constexpr float SCALE_  = 0.125f;    // 1/sqrt(64)
constexpr float GELU_C_ = 0.7978845608028654f;

// ---------------------------------------------------------------------------
// Scratch (device globals: no allocation allowed)
// ---------------------------------------------------------------------------
__device__ float g_mod [B_ * MODD_];
__device__ float g_qn  [B_ * S_ * D_];
__device__ float g_kvn [B_ * K_ * D_];
__device__ float g_q   [B_ * S_ * D_];
__device__ float g_kv  [B_ * K_ * 2 * D_];
__device__ float g_attn[B_ * S_ * D_];
__device__ float g_o   [B_ * S_ * D_];
__device__ float g_x1  [B_ * S_ * D_];
__device__ float g_hn  [B_ * S_ * D_];
__device__ float g_h1  [B_ * S_ * HID_];
__device__ float g_h2  [B_ * S_ * D_];

// ---------------------------------------------------------------------------
// mod = t_cond @ adaW + adab   -> g_mod [B, 6144]
// One block = 256 output columns, all 4 batches at once (adaW read once).
// ---------------------------------------------------------------------------
__global__ __launch_bounds__(256) void mod_kernel(
    const float* __restrict__ t, const float* __restrict__ W,
    const float* __restrict__ bias)
{
    __shared__ float ts[B_ * COND_];          // 16 KB
    const int j = blockIdx.x * 256 + threadIdx.x;
    for (int i = threadIdx.x; i < B_ * COND_; i += 256) ts[i] = t[i];
    __syncthreads();

    float acc[B_];
    const float bz = bias[j];
#pragma unroll
    for (int b = 0; b < B_; ++b) acc[b] = bz;

    for (int c = 0; c < COND_; ++c) {
        const float w = W[(size_t)c * MODD_ + j];
#pragma unroll
        for (int b = 0; b < B_; ++b) acc[b] += ts[b * COND_ + c] * w;
    }
#pragma unroll
    for (int b = 0; b < B_; ++b) g_mod[b * MODD_ + j] = acc[b];
}

// ---------------------------------------------------------------------------
// LayerNorm (+ optional adaLN modulation): one block per row of 1024
//   y = (x - mu) * rsqrt(var + eps) * w        [* (1 + sc) + sh if useMod]
// ---------------------------------------------------------------------------
__global__ __launch_bounds__(256) void ln_kernel(
    const float* __restrict__ x, const float* __restrict__ w,
    float* __restrict__ out, int shOff, int scOff, int useMod)
{
    const int row = blockIdx.x;
    const int b   = row >> 10;                // S_ = K_ = 1024 rows per batch
    const int t   = threadIdx.x;
    const float4 v = *((const float4*)(x + (size_t)row * D_) + t);

    float sum = v.x + v.y + v.z + v.w;
    float sq  = v.x*v.x + v.y*v.y + v.z*v.z + v.w*v.w;
#pragma unroll
    for (int o = 16; o; o >>= 1) {
        sum += __shfl_xor_sync(~0u, sum, o);
        sq  += __shfl_xor_sync(~0u, sq,  o);
    }
    __shared__ float s1[8], s2[8], st[2];
    const int wid = t >> 5, lane = t & 31;
    if (lane == 0) { s1[wid] = sum; s2[wid] = sq; }
    __syncthreads();
    if (t == 0) {
        float a = 0.f, c = 0.f;
#pragma unroll
        for (int i = 0; i < 8; ++i) { a += s1[i]; c += s2[i]; }
        const float mean = a * (1.0f / D_);
        const float var  = c * (1.0f / D_) - mean * mean;
        st[0] = mean; st[1] = rsqrtf(var + EPS_);
    }
    __syncthreads();
    const float mean = st[0], rstd = st[1];
    const int d = t * 4;
    const float4 w4 = *(const float4*)(w + d);
    float4 y;
    y.x = (v.x - mean) * rstd * w4.x;
    y.y = (v.y - mean) * rstd * w4.y;
    y.z = (v.z - mean) * rstd * w4.z;
    y.w = (v.w - mean) * rstd * w4.w;
    if (useMod) {
        const float* mb = g_mod + b * MODD_;
        const float4 sh = *(const float4*)(mb + shOff + d);
        const float4 sc = *(const float4*)(mb + scOff + d);
        y.x = y.x * (1.f + sc.x) + sh.x;
        y.y = y.y * (1.f + sc.y) + sh.y;
        y.z = y.z * (1.f + sc.z) + sh.z;
        y.w = y.w * (1.f + sc.w) + sh.w;
    }
    *((float4*)(out + (size_t)row * D_) + t) = y;
}

// ---------------------------------------------------------------------------
// SGEMM: C[M,N] = A[M,K] @ B[K,N] (both row-major), 128x128x8 tile, 8x8/thread
// MODE: 0 = plain, 1 = +bias, 2 = gelu_tanh(+bias)
// M,N multiples of 128; K multiple of 8.
// ---------------------------------------------------------------------------
__device__ __forceinline__ float gelu_tanh_f(float x)
{
    const float x3 = x * x * x;
    const float t  = tanhf(GELU_C_ * (x + 0.044715f * x3));
    return 0.5f * x * (1.0f + t);
}

template <int MODE>
__global__ __launch_bounds__(256, 2) void sgemm_k(
    const float* __restrict__ A, const float* __restrict__ Bm,
    const float* __restrict__ bias, float* __restrict__ C,
    int M, int N, int Kd)
{
    __shared__ float As[8][128];
    __shared__ float Bs[8][128];

    const int tid = threadIdx.x;
    const int tx  = tid & 15, ty = tid >> 4;
    const int aRow = tid >> 1, aCol = (tid & 1) * 4;
    const int bRow = tid >> 5, bCol = (tid & 31) * 4;

    const float* Ag = A  + (size_t)(blockIdx.y * 128 + aRow) * Kd + aCol;
    const float* Bg = Bm + (size_t)bRow * N + blockIdx.x * 128 + bCol;

    float acc[8][8];
#pragma unroll
    for (int i = 0; i < 8; ++i)
#pragma unroll
        for (int j = 0; j < 8; ++j) acc[i][j] = 0.f;

    for (int k0 = 0; k0 < Kd; k0 += 8) {
        const float4 a4 = *(const float4*)(Ag + k0);
        As[aCol + 0][aRow] = a4.x;
        As[aCol + 1][aRow] = a4.y;
        As[aCol + 2][aRow] = a4.z;
        As[aCol + 3][aRow] = a4.w;
        *(float4*)(&Bs[bRow][bCol]) = *(const float4*)(Bg + (size_t)k0 * N);
        __syncthreads();
#pragma unroll
        for (int kk = 0; kk < 8; ++kk) {
            float ar[8], br[8];
            *(float4*)(ar)     = *(const float4*)(&As[kk][ty * 8]);
            *(float4*)(ar + 4) = *(const float4*)(&As[kk][ty * 8 + 4]);
            *(float4*)(br)     = *(const float4*)(&Bs[kk][tx * 8]);
            *(float4*)(br + 4) = *(const float4*)(&Bs[kk][tx * 8 + 4]);
#pragma unroll
            for (int i = 0; i < 8; ++i)
#pragma unroll
                for (int j = 0; j < 8; ++j) acc[i][j] += ar[i] * br[j];
        }
        __syncthreads();
    }

    const int rowC = blockIdx.y * 128 + ty * 8;
    const int colC = blockIdx.x * 128 + tx * 8;
#pragma unroll
    for (int i = 0; i < 8; ++i) {
        float* cp = C + (size_t)(rowC + i) * N + colC;
#pragma unroll
        for (int j4 = 0; j4 < 2; ++j4) {
            float4 r;
            float vv[4];
#pragma unroll
            for (int j = 0; j < 4; ++j) {
                float val = acc[i][j4 * 4 + j];
                if (MODE >= 1) val += bias[colC + j4 * 4 + j];
                if (MODE == 2) val = gelu_tanh_f(val);
                vv[j] = val;
            }
            r.x = vv[0]; r.y = vv[1]; r.z = vv[2]; r.w = vv[3];
            *(float4*)(cp + j4 * 4) = r;
        }
    }
}

// ---------------------------------------------------------------------------
// RoPE (in place) for q or k: grid over b*seq*H*32 (each thread does a pair)
// ---------------------------------------------------------------------------
__global__ void rope_kernel(float* __restrict__ x, const float* __restrict__ cosA,
                            const float* __restrict__ sinA, int rowStride, int n)
{
    const int idx = blockIdx.x * blockDim.x + threadIdx.x;
    if (idx >= n) return;
    const int d = idx & 31;
    const int h = (idx >> 5) & 15;
    const int r = idx >> 9;           // b*seq + s   (seq == 1024)
    const int s = r & 1023;
    float* p = x + (size_t)r * rowStride + h * HD_;
    const float x1 = p[d], x2 = p[d + 32];
    const float c1 = cosA[s * HD_ + d],      sv1 = sinA[s * HD_ + d];
    const float c2 = cosA[s * HD_ + d + 32], sv2 = sinA[s * HD_ + d + 32];
    p[d]      = x1 * c1 - x2 * sv1;
    p[d + 32] = x2 * c2 + x1 * sv2;
}

// ---------------------------------------------------------------------------
// Flash attention with group mask (attend where group_idx differs).
// Grid: (S/64, B*H). Block 256 = 16x16 threads, each owns a 4x4 tile.
// smem: Q(16K) + K/P(16K) + V(16K) = 48 KB exactly.
// ---------------------------------------------------------------------------
__global__ __launch_bounds__(256) void attn_kernel(
    const float* __restrict__ Q, const float* __restrict__ KV,
    const int* __restrict__ gidx, float* __restrict__ Out)
{
    __shared__ float Qs[64 * 64];
    __shared__ float Ks[64 * 64];   // K tile, later reused for P
    __shared__ float Vs[64 * 64];

    const int tid = threadIdx.x;
    const int tx = tid & 15, ty = tid >> 4;
    const int bh = blockIdx.y;
    const int b = bh >> 4, h = bh & 15;
    const int q0 = blockIdx.x * 64;
    const int r0 = ty * 4, c0 = tx * 4;

    // load Q (pre-scaled by 1/sqrt(HD))
    for (int i = tid; i < 64 * 16; i += 256) {
        const int r = i >> 4, c4 = (i & 15) << 2;
        float4 v = *(const float4*)(Q + (size_t)(b * S_ + q0 + r) * D_ + h * HD_ + c4);
        v.x *= SCALE_; v.y *= SCALE_; v.z *= SCALE_; v.w *= SCALE_;
        *(float4*)(Qs + r * 64 + c4) = v;
    }
    int gq[4];
#pragma unroll
    for (int i = 0; i < 4; ++i) gq[i] = gidx[b * S_ + q0 + r0 + i];

    float m[4], l[4], O[4][4];
#pragma unroll
    for (int i = 0; i < 4; ++i) {
        m[i] = -1e30f; l[i] = 0.f;
#pragma unroll
        for (int j = 0; j < 4; ++j) O[i][j] = 0.f;
    }
    __syncthreads();

    for (int kc = 0; kc < K_; kc += 64) {
        // load K and V tiles
        for (int i = tid; i < 64 * 16; i += 256) {
            const int r = i >> 4, c4 = (i & 15) << 2;
            const float* base = KV + (size_t)(b * K_ + kc + r) * (2 * D_) + h * HD_ + c4;
            *(float4*)(Ks + r * 64 + c4) = *(const float4*)(base);
            *(float4*)(Vs + r * 64 + c4) = *(const float4*)(base + D_);
        }
        __syncthreads();

        // S = Q K^T (scaled)
        float s[4][4];
#pragma unroll
        for (int i = 0; i < 4; ++i)
#pragma unroll
            for (int j = 0; j < 4; ++j) s[i][j] = 0.f;
        for (int d0 = 0; d0 < 64; d0 += 4) {
            float4 qv[4], kv4[4];
#pragma unroll
            for (int i = 0; i < 4; ++i) qv[i]  = *(const float4*)(Qs + (r0 + i) * 64 + d0);
#pragma unroll
            for (int j = 0; j < 4; ++j) kv4[j] = *(const float4*)(Ks + (c0 + j) * 64 + d0);
#pragma unroll
            for (int i = 0; i < 4; ++i)
#pragma unroll
                for (int j = 0; j < 4; ++j)
                    s[i][j] += qv[i].x * kv4[j].x + qv[i].y * kv4[j].y
                             + qv[i].z * kv4[j].z + qv[i].w * kv4[j].w;
        }

        // group mask: keep only where gq != gk (reference semantics)
        int gk[4];
#pragma unroll
        for (int j = 0; j < 4; ++j) gk[j] = __ldg(gidx + b * K_ + kc + c0 + j);
#pragma unroll
        for (int i = 0; i < 4; ++i)
#pragma unroll
            for (int j = 0; j < 4; ++j)
                if (gq[i] == gk[j]) s[i][j] = -1000000000.0f;

        // online softmax update (rows reduced across the 16 tx lanes)
#pragma unroll
        for (int i = 0; i < 4; ++i) {
            float mi = fmaxf(fmaxf(s[i][0], s[i][1]), fmaxf(s[i][2], s[i][3]));
#pragma unroll
            for (int o = 1; o < 16; o <<= 1) mi = fmaxf(mi, __shfl_xor_sync(~0u, mi, o));
            const float mn  = fmaxf(m[i], mi);
            const float fac = __expf(m[i] - mn);
            float rs = 0.f;
#pragma unroll
            for (int j = 0; j < 4; ++j) { s[i][j] = __expf(s[i][j] - mn); rs += s[i][j]; }
#pragma unroll
            for (int o = 1; o < 16; o <<= 1) rs += __shfl_xor_sync(~0u, rs, o);
            l[i] = l[i] * fac + rs;
#pragma unroll
            for (int j = 0; j < 4; ++j) O[i][j] *= fac;
            m[i] = mn;
        }
        __syncthreads();   // done reading K tile

        // write P into Ks
#pragma unroll
        for (int i = 0; i < 4; ++i)
            *(float4*)(Ks + (r0 + i) * 64 + c0) = make_float4(s[i][0], s[i][1], s[i][2], s[i][3]);
        __syncthreads();

        // O += P @ V
        for (int kk = 0; kk < 64; kk += 4) {
            float4 pr[4];
#pragma unroll
            for (int i = 0; i < 4; ++i) pr[i] = *(const float4*)(Ks + (r0 + i) * 64 + kk);
#pragma unroll
            for (int t2 = 0; t2 < 4; ++t2) {
                const float4 vv = *(const float4*)(Vs + (kk + t2) * 64 + c0);
#pragma unroll
                for (int i = 0; i < 4; ++i) {
                    const float pv = (t2 == 0) ? pr[i].x : (t2 == 1) ? pr[i].y
                                   : (t2 == 2) ? pr[i].z : pr[i].w;
                    O[i][0] += pv * vv.x; O[i][1] += pv * vv.y;
                    O[i][2] += pv * vv.z; O[i][3] += pv * vv.w;
                }
            }
        }
        __syncthreads();   // before next chunk overwrites tiles
    }

    // write out: attn[b, q, h, :]
#pragma unroll
    for (int i = 0; i < 4; ++i) {
        const float inv = 1.0f / l[i];
        float4 r = make_float4(O[i][0] * inv, O[i][1] * inv, O[i][2] * inv, O[i][3] * inv);
        *(float4*)(Out + (size_t)(b * S_ + q0 + r0 + i) * D_ + h * HD_ + c0) = r;
    }
}

// ---------------------------------------------------------------------------
// Gated residual: dst = qe ? g * go + xres : xres   (g = mod[b, gOff + d])
// ---------------------------------------------------------------------------
__global__ void resid_kernel(const float* __restrict__ go, const float* __restrict__ xres,
                             const int* __restrict__ qe, float* __restrict__ dst, int gOff)
{
    const int i4 = blockIdx.x * blockDim.x + threadIdx.x;   // < B*S*D/4
    const int e   = i4 * 4;
    const int d   = e & (D_ - 1);
    const int row = e >> 10;          // b*S + s
    const int b   = row >> 10;
    const float4 o  = *(const float4*)(go + e);
    const float4 xr = *(const float4*)(xres + e);
    float4 r;
    if (qe[row]) {
        const float4 g = *(const float4*)(g_mod + b * MODD_ + gOff + d);
        r.x = g.x * o.x + xr.x; r.y = g.y * o.y + xr.y;
        r.z = g.z * o.z + xr.z; r.w = g.w * o.w + xr.w;
    } else {
        r = xr;
    }
    *(float4*)(dst + e) = r;
}

// ---------------------------------------------------------------------------
// Host launcher
// ---------------------------------------------------------------------------
extern "C" void kernel_launch(void* const* d_in, const int* in_sizes, int n_in,
                              void* d_out, int out_size)
{
    const float* q_x    = (const float*)d_in[0];
    const float* kv_x   = (const float*)d_in[1];
    const float* t_cond = (const float*)d_in[2];
    const float* cos_q  = (const float*)d_in[3];
    const float* sin_q  = (const float*)d_in[4];
    const float* cos_k  = (const float*)d_in[5];
    const float* sin_k  = (const float*)d_in[6];
    const int*   gidx   = (const int*)d_in[7];
    const int*   qe     = (const int*)d_in[8];
    const float* qn_w   = (const float*)d_in[9];
    const float* kvn_w  = (const float*)d_in[10];
    const float* n2_w   = (const float*)d_in[11];
    const float* Wq     = (const float*)d_in[12];
    const float* Wkv    = (const float*)d_in[13];
    const float* Wo     = (const float*)d_in[14];
    const float* W1     = (const float*)d_in[15];
    const float* b1     = (const float*)d_in[16];
    const float* W2     = (const float*)d_in[17];
    const float* b2     = (const float*)d_in[18];
    const float* adaW   = (const float*)d_in[19];
    const float* adab   = (const float*)d_in[20];

    float *p_qn, *p_kvn, *p_q, *p_kv, *p_attn, *p_o, *p_x1, *p_hn, *p_h1, *p_h2;
    cudaGetSymbolAddress((void**)&p_qn,   g_qn);
    cudaGetSymbolAddress((void**)&p_kvn,  g_kvn);
    cudaGetSymbolAddress((void**)&p_q,    g_q);
    cudaGetSymbolAddress((void**)&p_kv,   g_kv);
    cudaGetSymbolAddress((void**)&p_attn, g_attn);
    cudaGetSymbolAddress((void**)&p_o,    g_o);
    cudaGetSymbolAddress((void**)&p_x1,   g_x1);
    cudaGetSymbolAddress((void**)&p_hn,   g_hn);
    cudaGetSymbolAddress((void**)&p_h1,   g_h1);
    cudaGetSymbolAddress((void**)&p_h2,   g_h2);

    const int M = B_ * S_;                   // 4096

    // 1. adaLN modulation
    mod_kernel<<<MODD_ / 256, 256>>>(t_cond, adaW, adab);

    // 2. LayerNorms (+ msa modulation for q)
    ln_kernel<<<M, 256>>>(q_x,  qn_w,  p_qn,  0, D_, 1);
    ln_kernel<<<M, 256>>>(kv_x, kvn_w, p_kvn, 0, 0,  0);

    // 3. Projections
    sgemm_k<0><<<dim3(D_ / 128,      M / 128), 256>>>(p_qn,  Wq,  nullptr, p_q,  M, D_,      D_);
    sgemm_k<0><<<dim3(2 * D_ / 128,  M / 128), 256>>>(p_kvn, Wkv, nullptr, p_kv, M, 2 * D_,  D_);

    // 4. RoPE (q and k in place)
    const int nrope = B_ * 1024 * H_ * 32;   // 2M pairs
    rope_kernel<<<nrope / 256, 256>>>(p_q,  cos_q, sin_q, D_,     nrope);
    rope_kernel<<<nrope / 256, 256>>>(p_kv, cos_k, sin_k, 2 * D_, nrope);

    // 5. Attention
    attn_kernel<<<dim3(S_ / 64, B_ * H_), 256>>>(p_q, p_kv, gidx, p_attn);

    // 6. Output projection + gated residual -> x_mid
    sgemm_k<0><<<dim3(D_ / 128, M / 128), 256>>>(p_attn, Wo, nullptr, p_o, M, D_, D_);
    resid_kernel<<<(M * D_ / 4) / 256, 256>>>(p_o, q_x, qe, p_x1, 2 * D_);

    // 7. MLP
    ln_kernel<<<M, 256>>>(p_x1, n2_w, p_hn, 3 * D_, 4 * D_, 1);
    sgemm_k<2><<<dim3(HID_ / 128, M / 128), 256>>>(p_hn, W1, b1, p_h1, M, HID_, D_);
    sgemm_k<1><<<dim3(D_ / 128,   M / 128), 256>>>(p_h1, W2, b2, p_h2, M, D_, HID_);

    // 8. Final gated residual -> output
    resid_kernel<<<(M * D_ / 4) / 256, 256>>>(p_h2, p_x1, qe, (float*)d_out, 5 * D_);
}

// round 6
// speedup vs baseline: 1.7362x; 1.7362x over previous
#include <cuda_runtime.h>
#include <cuda_bf16.h>
#include <math.h>

// ---------------------------------------------------------------------------
// Problem constants
// ---------------------------------------------------------------------------
constexpr int B_    = 4;
constexpr int S_    = 1024;
constexpr int K_    = 1024;
constexpr int D_    = 1024;
constexpr int H_    = 16;
constexpr int HD_   = 64;
constexpr int COND_ = 1024;
constexpr int HID_  = 4096;          // MR * D
constexpr int MODD_ = 6 * D_;        // 6144
constexpr float EPS_    = 1e-5f;
constexpr float SCALE_  = 0.125f;    // 1/sqrt(64)
constexpr float GELU_C_ = 0.7978845608028654f;

// ---------------------------------------------------------------------------
// Scratch (device globals: no allocation allowed)
// ---------------------------------------------------------------------------
__device__ float g_mod [B_ * MODD_];
__device__ float g_qn  [B_ * S_ * D_];
__device__ float g_kvn [B_ * K_ * D_];
__device__ float g_q   [B_ * S_ * D_];
__device__ float g_kv  [B_ * K_ * 2 * D_];
__device__ float g_attn[B_ * S_ * D_];
__device__ float g_o   [B_ * S_ * D_];
__device__ float g_x1  [B_ * S_ * D_];
__device__ float g_hn  [B_ * S_ * D_];
__device__ float g_h1  [B_ * S_ * HID_];
__device__ float g_h2  [B_ * S_ * D_];

// ---------------------------------------------------------------------------
// mod = t_cond @ adaW + adab   -> g_mod [B, 6144]
// ---------------------------------------------------------------------------
__global__ __launch_bounds__(256) void mod_kernel(
    const float* __restrict__ t, const float* __restrict__ W,
    const float* __restrict__ bias)
{
    __shared__ float ts[B_ * COND_];          // 16 KB
    const int j = blockIdx.x * 256 + threadIdx.x;
    for (int i = threadIdx.x; i < B_ * COND_; i += 256) ts[i] = t[i];
    __syncthreads();

    float acc[B_];
    const float bz = bias[j];
#pragma unroll
    for (int b = 0; b < B_; ++b) acc[b] = bz;

    for (int c = 0; c < COND_; ++c) {
        const float w = W[(size_t)c * MODD_ + j];
#pragma unroll
        for (int b = 0; b < B_; ++b) acc[b] += ts[b * COND_ + c] * w;
    }
#pragma unroll
    for (int b = 0; b < B_; ++b) g_mod[b * MODD_ + j] = acc[b];
}

// ---------------------------------------------------------------------------
// LayerNorm (+ optional adaLN modulation): one block per row of 1024
// ---------------------------------------------------------------------------
__global__ __launch_bounds__(256) void ln_kernel(
    const float* __restrict__ x, const float* __restrict__ w,
    float* __restrict__ out, int shOff, int scOff, int useMod)
{
    const int row = blockIdx.x;
    const int b   = row >> 10;
    const int t   = threadIdx.x;
    const float4 v = *((const float4*)(x + (size_t)row * D_) + t);

    float sum = v.x + v.y + v.z + v.w;
    float sq  = v.x*v.x + v.y*v.y + v.z*v.z + v.w*v.w;
#pragma unroll
    for (int o = 16; o; o >>= 1) {
        sum += __shfl_xor_sync(~0u, sum, o);
        sq  += __shfl_xor_sync(~0u, sq,  o);
    }
    __shared__ float s1[8], s2[8], st[2];
    const int wid = t >> 5, lane = t & 31;
    if (lane == 0) { s1[wid] = sum; s2[wid] = sq; }
    __syncthreads();
    if (t == 0) {
        float a = 0.f, c = 0.f;
#pragma unroll
        for (int i = 0; i < 8; ++i) { a += s1[i]; c += s2[i]; }
        const float mean = a * (1.0f / D_);
        const float var  = c * (1.0f / D_) - mean * mean;
        st[0] = mean; st[1] = rsqrtf(var + EPS_);
    }
    __syncthreads();
    const float mean = st[0], rstd = st[1];
    const int d = t * 4;
    const float4 w4 = *(const float4*)(w + d);
    float4 y;
    y.x = (v.x - mean) * rstd * w4.x;
    y.y = (v.y - mean) * rstd * w4.y;
    y.z = (v.z - mean) * rstd * w4.z;
    y.w = (v.w - mean) * rstd * w4.w;
    if (useMod) {
        const float* mb = g_mod + b * MODD_;
        const float4 sh = *(const float4*)(mb + shOff + d);
        const float4 sc = *(const float4*)(mb + scOff + d);
        y.x = y.x * (1.f + sc.x) + sh.x;
        y.y = y.y * (1.f + sc.y) + sh.y;
        y.z = y.z * (1.f + sc.z) + sh.z;
        y.w = y.w * (1.f + sc.w) + sh.w;
    }
    *((float4*)(out + (size_t)row * D_) + t) = y;
}

// ---------------------------------------------------------------------------
// tf32 tensor-core GEMM: C[M,N] = A[M,K] @ B[K,N] row-major.
// 128x128 block tile, Ktile=16, 8 warps (64x32 warp tile), m16n8k8 tf32 mma.
// MODE: 0 = plain, 1 = +bias, 2 = gelu_tanh(+bias)
// M, N multiples of 128; K multiple of 16.
// ---------------------------------------------------------------------------
__device__ __forceinline__ float gelu_tanh_f(float x)
{
    const float x3 = x * x * x;
    const float t  = tanhf(GELU_C_ * (x + 0.044715f * x3));
    return 0.5f * x * (1.0f + t);
}

__device__ __forceinline__ float tf32r(float x)
{
    float r;
    asm("cvt.rna.tf32.f32 %0, %1;" : "=f"(r) : "f"(x));
    return r;
}

__device__ __forceinline__ float4 tf32r4(float4 v)
{
    v.x = tf32r(v.x); v.y = tf32r(v.y); v.z = tf32r(v.z); v.w = tf32r(v.w);
    return v;
}

__device__ __forceinline__ void mma_tf32(float* d, const unsigned* a, const unsigned* b)
{
    asm volatile(
        "mma.sync.aligned.m16n8k8.row.col.f32.tf32.tf32.f32 "
        "{%0,%1,%2,%3}, {%4,%5,%6,%7}, {%8,%9}, {%0,%1,%2,%3};\n"
        : "+f"(d[0]), "+f"(d[1]), "+f"(d[2]), "+f"(d[3])
        : "r"(a[0]), "r"(a[1]), "r"(a[2]), "r"(a[3]),
          "r"(b[0]), "r"(b[1]));
}

constexpr int ASTR = 20;    // padded A smem row stride (floats)
constexpr int BSTR = 136;   // padded B smem row stride (floats)

template <int MODE>
__global__ __launch_bounds__(256, 2) void mma_gemm(
    const float* __restrict__ A, const float* __restrict__ Bm,
    const float* __restrict__ bias, float* __restrict__ C,
    int M, int N, int Kd)
{
    __shared__ float As[2][128 * ASTR];   // 20480 B
    __shared__ float Bs[2][16 * BSTR];    // 17408 B

    const int tid   = threadIdx.x;
    const int lane  = tid & 31, wid = tid >> 5;
    const int warpM = wid >> 2, warpN = wid & 3;     // 2 x 4 warps
    const int quad  = lane >> 2, q4 = lane & 3;

    // global-load coordinates (tile-local)
    const int aR0 = tid >> 2;             // 0..63  (thread also does aR0+64)
    const int aK4 = (tid & 3) << 2;       // 0,4,8,12
    const int bK0 = tid >> 5;             // 0..7   (thread also does bK0+8)
    const int bN4 = lane << 2;            // 0..124

    const float* Ag = A  + (size_t)(blockIdx.y * 128 + aR0) * Kd + aK4;
    const float* Bg = Bm + (size_t)bK0 * N + blockIdx.x * 128 + bN4;

    float4 pa0, pa1, pb0, pb1;
    pa0 = *(const float4*)(Ag);
    pa1 = *(const float4*)(Ag + (size_t)64 * Kd);
    pb0 = *(const float4*)(Bg);
    pb1 = *(const float4*)(Bg + (size_t)8 * N);

    float acc[16][4];
#pragma unroll
    for (int i = 0; i < 16; ++i)
#pragma unroll
        for (int j = 0; j < 4; ++j) acc[i][j] = 0.f;

    // store tile 0 (tf32-rounded at store time)
    {
        *(float4*)(&As[0][aR0 * ASTR + aK4])        = tf32r4(pa0);
        *(float4*)(&As[0][(aR0 + 64) * ASTR + aK4]) = tf32r4(pa1);
        *(float4*)(&Bs[0][bK0 * BSTR + bN4])        = tf32r4(pb0);
        *(float4*)(&Bs[0][(bK0 + 8) * BSTR + bN4])  = tf32r4(pb1);
    }
    __syncthreads();

    const int ktiles = Kd >> 4;
    int buf = 0;

    for (int kt = 0; kt < ktiles; ++kt) {
        const bool more = (kt + 1) < ktiles;
        if (more) {
            const float* Ag2 = Ag + (kt + 1) * 16;
            const float* Bg2 = Bg + (size_t)(kt + 1) * 16 * N;
            pa0 = *(const float4*)(Ag2);
            pa1 = *(const float4*)(Ag2 + (size_t)64 * Kd);
            pb0 = *(const float4*)(Bg2);
            pb1 = *(const float4*)(Bg2 + (size_t)8 * N);
        }

        const float* Ab = &As[buf][(warpM * 64 + quad) * ASTR + q4];
        const float* Bb = &Bs[buf][q4 * BSTR + warpN * 32 + quad];

#pragma unroll
        for (int kk = 0; kk < 2; ++kk) {
            unsigned af[4][4], bf[4][2];
#pragma unroll
            for (int mi = 0; mi < 4; ++mi) {
                const float* p = Ab + mi * (16 * ASTR) + kk * 8;
                af[mi][0] = __float_as_uint(p[0]);
                af[mi][1] = __float_as_uint(p[8 * ASTR]);
                af[mi][2] = __float_as_uint(p[4]);
                af[mi][3] = __float_as_uint(p[8 * ASTR + 4]);
            }
#pragma unroll
            for (int ni = 0; ni < 4; ++ni) {
                const float* p = Bb + kk * (8 * BSTR) + ni * 8;
                bf[ni][0] = __float_as_uint(p[0]);
                bf[ni][1] = __float_as_uint(p[4 * BSTR]);
            }
#pragma unroll
            for (int mi = 0; mi < 4; ++mi)
#pragma unroll
                for (int ni = 0; ni < 4; ++ni)
                    mma_tf32(acc[mi * 4 + ni], af[mi], bf[ni]);
        }

        if (more) {
            const int nb = buf ^ 1;
            *(float4*)(&As[nb][aR0 * ASTR + aK4])        = tf32r4(pa0);
            *(float4*)(&As[nb][(aR0 + 64) * ASTR + aK4]) = tf32r4(pa1);
            *(float4*)(&Bs[nb][bK0 * BSTR + bN4])        = tf32r4(pb0);
            *(float4*)(&Bs[nb][(bK0 + 8) * BSTR + bN4])  = tf32r4(pb1);
            __syncthreads();
            buf = nb;
        }
    }

    // epilogue: c0,c1 at (row, col), c2,c3 at (row+8, col); col = 2*q4 (+1)
    const int rowB = blockIdx.y * 128 + warpM * 64 + quad;
    const int colB = blockIdx.x * 128 + warpN * 32 + q4 * 2;
#pragma unroll
    for (int mi = 0; mi < 4; ++mi) {
#pragma unroll
        for (int half = 0; half < 2; ++half) {
            const int row = rowB + mi * 16 + half * 8;
            float* cp = C + (size_t)row * N + colB;
#pragma unroll
            for (int ni = 0; ni < 4; ++ni) {
                float v0 = acc[mi * 4 + ni][half * 2];
                float v1 = acc[mi * 4 + ni][half * 2 + 1];
                if (MODE >= 1) {
                    v0 += bias[colB + ni * 8];
                    v1 += bias[colB + ni * 8 + 1];
                }
                if (MODE == 2) { v0 = gelu_tanh_f(v0); v1 = gelu_tanh_f(v1); }
                *(float2*)(cp + ni * 8) = make_float2(v0, v1);
            }
        }
    }
}

// ---------------------------------------------------------------------------
// RoPE (in place) for q or k
// ---------------------------------------------------------------------------
__global__ void rope_kernel(float* __restrict__ x, const float* __restrict__ cosA,
                            const float* __restrict__ sinA, int rowStride, int n)
{
    const int idx = blockIdx.x * blockDim.x + threadIdx.x;
    if (idx >= n) return;
    const int d = idx & 31;
    const int h = (idx >> 5) & 15;
    const int r = idx >> 9;
    const int s = r & 1023;
    float* p = x + (size_t)r * rowStride + h * HD_;
    const float x1 = p[d], x2 = p[d + 32];
    const float c1 = cosA[s * HD_ + d],      sv1 = sinA[s * HD_ + d];
    const float c2 = cosA[s * HD_ + d + 32], sv2 = sinA[s * HD_ + d + 32];
    p[d]      = x1 * c1 - x2 * sv1;
    p[d + 32] = x2 * c2 + x1 * sv2;
}

// ---------------------------------------------------------------------------
// Flash attention with group mask (attend where group_idx differs).
// ---------------------------------------------------------------------------
__global__ __launch_bounds__(256) void attn_kernel(
    const float* __restrict__ Q, const float* __restrict__ KV,
    const int* __restrict__ gidx, float* __restrict__ Out)
{
    __shared__ float Qs[64 * 64];
    __shared__ float Ks[64 * 64];
    __shared__ float Vs[64 * 64];

    const int tid = threadIdx.x;
    const int tx = tid & 15, ty = tid >> 4;
    const int bh = blockIdx.y;
    const int b = bh >> 4, h = bh & 15;
    const int q0 = blockIdx.x * 64;
    const int r0 = ty * 4, c0 = tx * 4;

    for (int i = tid; i < 64 * 16; i += 256) {
        const int r = i >> 4, c4 = (i & 15) << 2;
        float4 v = *(const float4*)(Q + (size_t)(b * S_ + q0 + r) * D_ + h * HD_ + c4);
        v.x *= SCALE_; v.y *= SCALE_; v.z *= SCALE_; v.w *= SCALE_;
        *(float4*)(Qs + r * 64 + c4) = v;
    }
    int gq[4];
#pragma unroll
    for (int i = 0; i < 4; ++i) gq[i] = gidx[b * S_ + q0 + r0 + i];

    float m[4], l[4], O[4][4];
#pragma unroll
    for (int i = 0; i < 4; ++i) {
        m[i] = -1e30f; l[i] = 0.f;
#pragma unroll
        for (int j = 0; j < 4; ++j) O[i][j] = 0.f;
    }
    __syncthreads();

    for (int kc = 0; kc < K_; kc += 64) {
        for (int i = tid; i < 64 * 16; i += 256) {
            const int r = i >> 4, c4 = (i & 15) << 2;
            const float* base = KV + (size_t)(b * K_ + kc + r) * (2 * D_) + h * HD_ + c4;
            *(float4*)(Ks + r * 64 + c4) = *(const float4*)(base);
            *(float4*)(Vs + r * 64 + c4) = *(const float4*)(base + D_);
        }
        __syncthreads();

        float s[4][4];
#pragma unroll
        for (int i = 0; i < 4; ++i)
#pragma unroll
            for (int j = 0; j < 4; ++j) s[i][j] = 0.f;
        for (int d0 = 0; d0 < 64; d0 += 4) {
            float4 qv[4], kv4[4];
#pragma unroll
            for (int i = 0; i < 4; ++i) qv[i]  = *(const float4*)(Qs + (r0 + i) * 64 + d0);
#pragma unroll
            for (int j = 0; j < 4; ++j) kv4[j] = *(const float4*)(Ks + (c0 + j) * 64 + d0);
#pragma unroll
            for (int i = 0; i < 4; ++i)
#pragma unroll
                for (int j = 0; j < 4; ++j)
                    s[i][j] += qv[i].x * kv4[j].x + qv[i].y * kv4[j].y
                             + qv[i].z * kv4[j].z + qv[i].w * kv4[j].w;
        }

        int gk[4];
#pragma unroll
        for (int j = 0; j < 4; ++j) gk[j] = __ldg(gidx + b * K_ + kc + c0 + j);
#pragma unroll
        for (int i = 0; i < 4; ++i)
#pragma unroll
            for (int j = 0; j < 4; ++j)
                if (gq[i] == gk[j]) s[i][j] = -1000000000.0f;

#pragma unroll
        for (int i = 0; i < 4; ++i) {
            float mi = fmaxf(fmaxf(s[i][0], s[i][1]), fmaxf(s[i][2], s[i][3]));
#pragma unroll
            for (int o = 1; o < 16; o <<= 1) mi = fmaxf(mi, __shfl_xor_sync(~0u, mi, o));
            const float mn  = fmaxf(m[i], mi);
            const float fac = __expf(m[i] - mn);
            float rs = 0.f;
#pragma unroll
            for (int j = 0; j < 4; ++j) { s[i][j] = __expf(s[i][j] - mn); rs += s[i][j]; }
#pragma unroll
            for (int o = 1; o < 16; o <<= 1) rs += __shfl_xor_sync(~0u, rs, o);
            l[i] = l[i] * fac + rs;
#pragma unroll
            for (int j = 0; j < 4; ++j) O[i][j] *= fac;
            m[i] = mn;
        }
        __syncthreads();

#pragma unroll
        for (int i = 0; i < 4; ++i)
            *(float4*)(Ks + (r0 + i) * 64 + c0) = make_float4(s[i][0], s[i][1], s[i][2], s[i][3]);
        __syncthreads();

        for (int kk = 0; kk < 64; kk += 4) {
            float4 pr[4];
#pragma unroll
            for (int i = 0; i < 4; ++i) pr[i] = *(const float4*)(Ks + (r0 + i) * 64 + kk);
#pragma unroll
            for (int t2 = 0; t2 < 4; ++t2) {
                const float4 vv = *(const float4*)(Vs + (kk + t2) * 64 + c0);
#pragma unroll
                for (int i = 0; i < 4; ++i) {
                    const float pv = (t2 == 0) ? pr[i].x : (t2 == 1) ? pr[i].y
                                   : (t2 == 2) ? pr[i].z : pr[i].w;
                    O[i][0] += pv * vv.x; O[i][1] += pv * vv.y;
                    O[i][2] += pv * vv.z; O[i][3] += pv * vv.w;
                }
            }
        }
        __syncthreads();
    }

#pragma unroll
    for (int i = 0; i < 4; ++i) {
        const float inv = 1.0f / l[i];
        float4 r = make_float4(O[i][0] * inv, O[i][1] * inv, O[i][2] * inv, O[i][3] * inv);
        *(float4*)(Out + (size_t)(b * S_ + q0 + r0 + i) * D_ + h * HD_ + c0) = r;
    }
}

// ---------------------------------------------------------------------------
// Gated residual: dst = qe ? g * go + xres : xres
// ---------------------------------------------------------------------------
__global__ void resid_kernel(const float* __restrict__ go, const float* __restrict__ xres,
                             const int* __restrict__ qe, float* __restrict__ dst, int gOff)
{
    const int i4 = blockIdx.x * blockDim.x + threadIdx.x;
    const int e   = i4 * 4;
    const int d   = e & (D_ - 1);
    const int row = e >> 10;
    const int b   = row >> 10;
    const float4 o  = *(const float4*)(go + e);
    const float4 xr = *(const float4*)(xres + e);
    float4 r;
    if (qe[row]) {
        const float4 g = *(const float4*)(g_mod + b * MODD_ + gOff + d);
        r.x = g.x * o.x + xr.x; r.y = g.y * o.y + xr.y;
        r.z = g.z * o.z + xr.z; r.w = g.w * o.w + xr.w;
    } else {
        r = xr;
    }
    *(float4*)(dst + e) = r;
}

// ---------------------------------------------------------------------------
// Host launcher
// ---------------------------------------------------------------------------
extern "C" void kernel_launch(void* const* d_in, const int* in_sizes, int n_in,
                              void* d_out, int out_size)
{
    const float* q_x    = (const float*)d_in[0];
    const float* kv_x   = (const float*)d_in[1];
    const float* t_cond = (const float*)d_in[2];
    const float* cos_q  = (const float*)d_in[3];
    const float* sin_q  = (const float*)d_in[4];
    const float* cos_k  = (const float*)d_in[5];
    const float* sin_k  = (const float*)d_in[6];
    const int*   gidx   = (const int*)d_in[7];
    const int*   qe     = (const int*)d_in[8];
    const float* qn_w   = (const float*)d_in[9];
    const float* kvn_w  = (const float*)d_in[10];
    const float* n2_w   = (const float*)d_in[11];
    const float* Wq     = (const float*)d_in[12];
    const float* Wkv    = (const float*)d_in[13];
    const float* Wo     = (const float*)d_in[14];
    const float* W1     = (const float*)d_in[15];
    const float* b1     = (const float*)d_in[16];
    const float* W2     = (const float*)d_in[17];
    const float* b2     = (const float*)d_in[18];
    const float* adaW   = (const float*)d_in[19];
    const float* adab   = (const float*)d_in[20];

    float *p_qn, *p_kvn, *p_q, *p_kv, *p_attn, *p_o, *p_x1, *p_hn, *p_h1, *p_h2;
    cudaGetSymbolAddress((void**)&p_qn,   g_qn);
    cudaGetSymbolAddress((void**)&p_kvn,  g_kvn);
    cudaGetSymbolAddress((void**)&p_q,    g_q);
    cudaGetSymbolAddress((void**)&p_kv,   g_kv);
    cudaGetSymbolAddress((void**)&p_attn, g_attn);
    cudaGetSymbolAddress((void**)&p_o,    g_o);
    cudaGetSymbolAddress((void**)&p_x1,   g_x1);
    cudaGetSymbolAddress((void**)&p_hn,   g_hn);
    cudaGetSymbolAddress((void**)&p_h1,   g_h1);
    cudaGetSymbolAddress((void**)&p_h2,   g_h2);

    const int M = B_ * S_;                   // 4096

    // 1. adaLN modulation
    mod_kernel<<<MODD_ / 256, 256>>>(t_cond, adaW, adab);

    // 2. LayerNorms (+ msa modulation for q)
    ln_kernel<<<M, 256>>>(q_x,  qn_w,  p_qn,  0, D_, 1);
    ln_kernel<<<M, 256>>>(kv_x, kvn_w, p_kvn, 0, 0,  0);

    // 3. Projections (tf32 tensor cores)
    mma_gemm<0><<<dim3(D_ / 128,      M / 128), 256>>>(p_qn,  Wq,  nullptr, p_q,  M, D_,      D_);
    mma_gemm<0><<<dim3(2 * D_ / 128,  M / 128), 256>>>(p_kvn, Wkv, nullptr, p_kv, M, 2 * D_,  D_);

    // 4. RoPE (q and k in place)
    const int nrope = B_ * 1024 * H_ * 32;   // 2M pairs
    rope_kernel<<<nrope / 256, 256>>>(p_q,  cos_q, sin_q, D_,     nrope);
    rope_kernel<<<nrope / 256, 256>>>(p_kv, cos_k, sin_k, 2 * D_, nrope);

    // 5. Attention
    attn_kernel<<<dim3(S_ / 64, B_ * H_), 256>>>(p_q, p_kv, gidx, p_attn);

    // 6. Output projection + gated residual -> x_mid
    mma_gemm<0><<<dim3(D_ / 128, M / 128), 256>>>(p_attn, Wo, nullptr, p_o, M, D_, D_);
    resid_kernel<<<(M * D_ / 4) / 256, 256>>>(p_o, q_x, qe, p_x1, 2 * D_);

    // 7. MLP
    ln_kernel<<<M, 256>>>(p_x1, n2_w, p_hn, 3 * D_, 4 * D_, 1);
    mma_gemm<2><<<dim3(HID_ / 128, M / 128), 256>>>(p_hn, W1, b1, p_h1, M, HID_, D_);
    mma_gemm<1><<<dim3(D_ / 128,   M / 128), 256>>>(p_h1, W2, b2, p_h2, M, D_, HID_);

    // 8. Final gated residual -> output
    resid_kernel<<<(M * D_ / 4) / 256, 256>>>(p_h2, p_x1, qe, (float*)d_out, 5 * D_);
}

// round 7
// speedup vs baseline: 3.0920x; 1.7809x over previous
#include <cuda_runtime.h>
#include <cuda_bf16.h>
#include <math.h>

// ---------------------------------------------------------------------------
// Problem constants
// ---------------------------------------------------------------------------
constexpr int B_    = 4;
constexpr int S_    = 1024;
constexpr int K_    = 1024;
constexpr int D_    = 1024;
constexpr int H_    = 16;
constexpr int HD_   = 64;
constexpr int COND_ = 1024;
constexpr int HID_  = 4096;          // MR * D
constexpr int MODD_ = 6 * D_;        // 6144
constexpr float EPS_    = 1e-5f;
constexpr float SCALE_  = 0.125f;    // 1/sqrt(64)
constexpr float GELU_C_ = 0.7978845608028654f;

// ---------------------------------------------------------------------------
// Scratch (device globals: no allocation allowed)
// ---------------------------------------------------------------------------
__device__ float g_mod [B_ * MODD_];
__device__ float g_qn  [B_ * S_ * D_];
__device__ float g_kvn [B_ * K_ * D_];
__device__ float g_q   [B_ * S_ * D_];
__device__ float g_kv  [B_ * K_ * 2 * D_];
__device__ float g_attn[B_ * S_ * D_];
__device__ float g_o   [B_ * S_ * D_];
__device__ float g_x1  [B_ * S_ * D_];
__device__ float g_hn  [B_ * S_ * D_];
__device__ float g_h1  [B_ * S_ * HID_];
__device__ float g_h2  [B_ * S_ * D_];

// ---------------------------------------------------------------------------
// mod = t_cond @ adaW + adab   -> g_mod [B, 6144]
// ---------------------------------------------------------------------------
__global__ __launch_bounds__(256) void mod_kernel(
    const float* __restrict__ t, const float* __restrict__ W,
    const float* __restrict__ bias)
{
    __shared__ float ts[B_ * COND_];          // 16 KB
    const int j = blockIdx.x * 256 + threadIdx.x;
    for (int i = threadIdx.x; i < B_ * COND_; i += 256) ts[i] = t[i];
    __syncthreads();

    float acc[B_];
    const float bz = bias[j];
#pragma unroll
    for (int b = 0; b < B_; ++b) acc[b] = bz;

    for (int c = 0; c < COND_; ++c) {
        const float w = W[(size_t)c * MODD_ + j];
#pragma unroll
        for (int b = 0; b < B_; ++b) acc[b] += ts[b * COND_ + c] * w;
    }
#pragma unroll
    for (int b = 0; b < B_; ++b) g_mod[b * MODD_ + j] = acc[b];
}

// ---------------------------------------------------------------------------
// LayerNorm (+ optional adaLN modulation): one block per row of 1024
// ---------------------------------------------------------------------------
__global__ __launch_bounds__(256) void ln_kernel(
    const float* __restrict__ x, const float* __restrict__ w,
    float* __restrict__ out, int shOff, int scOff, int useMod)
{
    const int row = blockIdx.x;
    const int b   = row >> 10;
    const int t   = threadIdx.x;
    const float4 v = *((const float4*)(x + (size_t)row * D_) + t);

    float sum = v.x + v.y + v.z + v.w;
    float sq  = v.x*v.x + v.y*v.y + v.z*v.z + v.w*v.w;
#pragma unroll
    for (int o = 16; o; o >>= 1) {
        sum += __shfl_xor_sync(~0u, sum, o);
        sq  += __shfl_xor_sync(~0u, sq,  o);
    }
    __shared__ float s1[8], s2[8], st[2];
    const int wid = t >> 5, lane = t & 31;
    if (lane == 0) { s1[wid] = sum; s2[wid] = sq; }
    __syncthreads();
    if (t == 0) {
        float a = 0.f, c = 0.f;
#pragma unroll
        for (int i = 0; i < 8; ++i) { a += s1[i]; c += s2[i]; }
        const float mean = a * (1.0f / D_);
        const float var  = c * (1.0f / D_) - mean * mean;
        st[0] = mean; st[1] = rsqrtf(var + EPS_);
    }
    __syncthreads();
    const float mean = st[0], rstd = st[1];
    const int d = t * 4;
    const float4 w4 = *(const float4*)(w + d);
    float4 y;
    y.x = (v.x - mean) * rstd * w4.x;
    y.y = (v.y - mean) * rstd * w4.y;
    y.z = (v.z - mean) * rstd * w4.z;
    y.w = (v.w - mean) * rstd * w4.w;
    if (useMod) {
        const float* mb = g_mod + b * MODD_;
        const float4 sh = *(const float4*)(mb + shOff + d);
        const float4 sc = *(const float4*)(mb + scOff + d);
        y.x = y.x * (1.f + sc.x) + sh.x;
        y.y = y.y * (1.f + sc.y) + sh.y;
        y.z = y.z * (1.f + sc.z) + sh.z;
        y.w = y.w * (1.f + sc.w) + sh.w;
    }
    *((float4*)(out + (size_t)row * D_) + t) = y;
}

// ---------------------------------------------------------------------------
// tf32 helpers
// ---------------------------------------------------------------------------
__device__ __forceinline__ float gelu_tanh_f(float x)
{
    const float x3 = x * x * x;
    const float t  = tanhf(GELU_C_ * (x + 0.044715f * x3));
    return 0.5f * x * (1.0f + t);
}

__device__ __forceinline__ float tf32r(float x)
{
    float r;
    asm("cvt.rna.tf32.f32 %0, %1;" : "=f"(r) : "f"(x));
    return r;
}

__device__ __forceinline__ float4 tf32r4(float4 v)
{
    v.x = tf32r(v.x); v.y = tf32r(v.y); v.z = tf32r(v.z); v.w = tf32r(v.w);
    return v;
}

__device__ __forceinline__ void mma_tf32(float* d, const unsigned* a, const unsigned* b)
{
    asm volatile(
        "mma.sync.aligned.m16n8k8.row.col.f32.tf32.tf32.f32 "
        "{%0,%1,%2,%3}, {%4,%5,%6,%7}, {%8,%9}, {%0,%1,%2,%3};\n"
        : "+f"(d[0]), "+f"(d[1]), "+f"(d[2]), "+f"(d[3])
        : "r"(a[0]), "r"(a[1]), "r"(a[2]), "r"(a[3]),
          "r"(b[0]), "r"(b[1]));
}

// ---------------------------------------------------------------------------
// tf32 tensor-core GEMM (unchanged from R5)
// ---------------------------------------------------------------------------
constexpr int ASTR = 20;
constexpr int BSTR = 136;

template <int MODE>
__global__ __launch_bounds__(256, 2) void mma_gemm(
    const float* __restrict__ A, const float* __restrict__ Bm,
    const float* __restrict__ bias, float* __restrict__ C,
    int M, int N, int Kd)
{
    __shared__ float As[2][128 * ASTR];
    __shared__ float Bs[2][16 * BSTR];

    const int tid   = threadIdx.x;
    const int lane  = tid & 31, wid = tid >> 5;
    const int warpM = wid >> 2, warpN = wid & 3;
    const int quad  = lane >> 2, q4 = lane & 3;

    const int aR0 = tid >> 2;
    const int aK4 = (tid & 3) << 2;
    const int bK0 = tid >> 5;
    const int bN4 = lane << 2;

    const float* Ag = A  + (size_t)(blockIdx.y * 128 + aR0) * Kd + aK4;
    const float* Bg = Bm + (size_t)bK0 * N + blockIdx.x * 128 + bN4;

    float4 pa0, pa1, pb0, pb1;
    pa0 = *(const float4*)(Ag);
    pa1 = *(const float4*)(Ag + (size_t)64 * Kd);
    pb0 = *(const float4*)(Bg);
    pb1 = *(const float4*)(Bg + (size_t)8 * N);

    float acc[16][4];
#pragma unroll
    for (int i = 0; i < 16; ++i)
#pragma unroll
        for (int j = 0; j < 4; ++j) acc[i][j] = 0.f;

    {
        *(float4*)(&As[0][aR0 * ASTR + aK4])        = tf32r4(pa0);
        *(float4*)(&As[0][(aR0 + 64) * ASTR + aK4]) = tf32r4(pa1);
        *(float4*)(&Bs[0][bK0 * BSTR + bN4])        = tf32r4(pb0);
        *(float4*)(&Bs[0][(bK0 + 8) * BSTR + bN4])  = tf32r4(pb1);
    }
    __syncthreads();

    const int ktiles = Kd >> 4;
    int buf = 0;

    for (int kt = 0; kt < ktiles; ++kt) {
        const bool more = (kt + 1) < ktiles;
        if (more) {
            const float* Ag2 = Ag + (kt + 1) * 16;
            const float* Bg2 = Bg + (size_t)(kt + 1) * 16 * N;
            pa0 = *(const float4*)(Ag2);
            pa1 = *(const float4*)(Ag2 + (size_t)64 * Kd);
            pb0 = *(const float4*)(Bg2);
            pb1 = *(const float4*)(Bg2 + (size_t)8 * N);
        }

        const float* Ab = &As[buf][(warpM * 64 + quad) * ASTR + q4];
        const float* Bb = &Bs[buf][q4 * BSTR + warpN * 32 + quad];

#pragma unroll
        for (int kk = 0; kk < 2; ++kk) {
            unsigned af[4][4], bf[4][2];
#pragma unroll
            for (int mi = 0; mi < 4; ++mi) {
                const float* p = Ab + mi * (16 * ASTR) + kk * 8;
                af[mi][0] = __float_as_uint(p[0]);
                af[mi][1] = __float_as_uint(p[8 * ASTR]);
                af[mi][2] = __float_as_uint(p[4]);
                af[mi][3] = __float_as_uint(p[8 * ASTR + 4]);
            }
#pragma unroll
            for (int ni = 0; ni < 4; ++ni) {
                const float* p = Bb + kk * (8 * BSTR) + ni * 8;
                bf[ni][0] = __float_as_uint(p[0]);
                bf[ni][1] = __float_as_uint(p[4 * BSTR]);
            }
#pragma unroll
            for (int mi = 0; mi < 4; ++mi)
#pragma unroll
                for (int ni = 0; ni < 4; ++ni)
                    mma_tf32(acc[mi * 4 + ni], af[mi], bf[ni]);
        }

        if (more) {
            const int nb = buf ^ 1;
            *(float4*)(&As[nb][aR0 * ASTR + aK4])        = tf32r4(pa0);
            *(float4*)(&As[nb][(aR0 + 64) * ASTR + aK4]) = tf32r4(pa1);
            *(float4*)(&Bs[nb][bK0 * BSTR + bN4])        = tf32r4(pb0);
            *(float4*)(&Bs[nb][(bK0 + 8) * BSTR + bN4])  = tf32r4(pb1);
            __syncthreads();
            buf = nb;
        }
    }

    const int rowB = blockIdx.y * 128 + warpM * 64 + quad;
    const int colB = blockIdx.x * 128 + warpN * 32 + q4 * 2;
#pragma unroll
    for (int mi = 0; mi < 4; ++mi) {
#pragma unroll
        for (int half = 0; half < 2; ++half) {
            const int row = rowB + mi * 16 + half * 8;
            float* cp = C + (size_t)row * N + colB;
#pragma unroll
            for (int ni = 0; ni < 4; ++ni) {
                float v0 = acc[mi * 4 + ni][half * 2];
                float v1 = acc[mi * 4 + ni][half * 2 + 1];
                if (MODE >= 1) {
                    v0 += bias[colB + ni * 8];
                    v1 += bias[colB + ni * 8 + 1];
                }
                if (MODE == 2) { v0 = gelu_tanh_f(v0); v1 = gelu_tanh_f(v1); }
                *(float2*)(cp + ni * 8) = make_float2(v0, v1);
            }
        }
    }
}

// ---------------------------------------------------------------------------
// RoPE (in place) for q or k
// ---------------------------------------------------------------------------
__global__ void rope_kernel(float* __restrict__ x, const float* __restrict__ cosA,
                            const float* __restrict__ sinA, int rowStride, int n)
{
    const int idx = blockIdx.x * blockDim.x + threadIdx.x;
    if (idx >= n) return;
    const int d = idx & 31;
    const int h = (idx >> 5) & 15;
    const int r = idx >> 9;
    const int s = r & 1023;
    float* p = x + (size_t)r * rowStride + h * HD_;
    const float x1 = p[d], x2 = p[d + 32];
    const float c1 = cosA[s * HD_ + d],      sv1 = sinA[s * HD_ + d];
    const float c2 = cosA[s * HD_ + d + 32], sv2 = sinA[s * HD_ + d + 32];
    p[d]      = x1 * c1 - x2 * sv1;
    p[d + 32] = x2 * c2 + x1 * sv2;
}

// ---------------------------------------------------------------------------
// Tensor-core flash attention (tf32 mma), group mask (attend iff gq != gk).
// Grid: (S/128, B*H), 256 threads (8 warps, 16 q-rows each).
// Dynamic smem, stride-64 rows, XOR swizzle col ^ ((row&3)<<3),
// k-pair interleave (t, t+4) -> (2t, 2t+1) so fragments load as LDS.64.
// ---------------------------------------------------------------------------
constexpr int QS_OFF = 0;            // Q   [128][64]  A-layout (q rows, d interleaved)
constexpr int KT_OFF = 128 * 64;     // K   [64][64]   (key rows, d interleaved)
constexpr int VT_OFF = 192 * 64;     // V^T [64][64]   (d rows, key interleaved)
constexpr int PS_OFF = 256 * 64;     // P   [128][64]  (q rows, key interleaved)
constexpr int GK_OFF = 384 * 64;     // 64 ints
constexpr int ATTN_SMEM_BYTES = (384 * 64 + 64) * 4;

__device__ __forceinline__ int ipos8(int k)   // (t,t+4) -> (2t,2t+1) within 8
{
    return ((k & 3) << 1) | ((k & 4) >> 2);
}

__global__ __launch_bounds__(256, 2) void attn_mma_kernel(
    const float* __restrict__ Q, const float* __restrict__ KV,
    const int* __restrict__ gidx, float* __restrict__ Out)
{
    extern __shared__ float sm[];
    float* Qs = sm + QS_OFF;
    float* Kt = sm + KT_OFF;
    float* Vt = sm + VT_OFF;
    float* Ps = sm + PS_OFF;
    int*  gks = (int*)(sm + GK_OFF);

    const int tid  = threadIdx.x;
    const int lane = tid & 31, w = tid >> 5;
    const int g = lane >> 2, t = lane & 3;
    const int bh = blockIdx.y, b = bh >> 4, h = bh & 15;
    const int q0 = blockIdx.x * 128;
    const int r0 = w * 16 + g;                 // rows r0, r0+8 (tile-local)
    const int xr = (g & 3) << 3;               // row-swizzle term (same for r0, r0+8)

    // ---- load Q tile (scaled, tf32-rounded) ----
    for (int i = tid; i < 128 * 16; i += 256) {
        const int r = i >> 4, d4 = (i & 15) << 2;
        float4 v = *(const float4*)(Q + (size_t)(b * S_ + q0 + r) * D_ + h * HD_ + d4);
        const int xb = r * 64 + (((d4 & ~7) ^ ((r & 3) << 3)) + ((d4 & 4) ? 1 : 0));
        Qs[xb + 0] = tf32r(v.x * SCALE_);
        Qs[xb + 2] = tf32r(v.y * SCALE_);
        Qs[xb + 4] = tf32r(v.z * SCALE_);
        Qs[xb + 6] = tf32r(v.w * SCALE_);
    }
    const int gq0 = gidx[b * S_ + q0 + r0];
    const int gq1 = gidx[b * S_ + q0 + r0 + 8];

    float m0 = -1e30f, m1 = -1e30f, l0 = 0.f, l1 = 0.f;
    float o[8][4];
#pragma unroll
    for (int i = 0; i < 8; ++i)
#pragma unroll
        for (int j = 0; j < 4; ++j) o[i][j] = 0.f;

    const int p0 = ipos8(2 * t);
    const int p1 = ipos8(2 * t + 1);

    for (int kc = 0; kc < K_; kc += 64) {
        __syncthreads();   // all warps done with previous K/V tiles

        // K tile: coalesced gmem (16 lanes per key row), d-interleaved store
        for (int i = tid; i < 64 * 16; i += 256) {
            const int r = i >> 4, d4 = (i & 15) << 2;
            float4 v = *(const float4*)(KV + (size_t)(b * K_ + kc + r) * (2 * D_) + h * HD_ + d4);
            const int xb = r * 64 + (((d4 & ~7) ^ ((r & 3) << 3)) + ((d4 & 4) ? 1 : 0));
            Kt[xb + 0] = tf32r(v.x);
            Kt[xb + 2] = tf32r(v.y);
            Kt[xb + 4] = tf32r(v.z);
            Kt[xb + 6] = tf32r(v.w);
        }
        // V tile: key-fast lanes (uncoalesced gmem, conflict-free transposed STS)
        for (int i = tid; i < 64 * 16; i += 256) {
            const int r = i & 63, d4 = (i >> 6) << 2;
            float4 v = *(const float4*)(KV + (size_t)(b * K_ + kc + r) * (2 * D_) + D_ + h * HD_ + d4);
            const int kpos = (r & ~7) | ipos8(r & 7);
            Vt[(d4 + 0) * 64 + (kpos ^ (0 << 3))] = tf32r(v.x);
            Vt[(d4 + 1) * 64 + (kpos ^ (1 << 3))] = tf32r(v.y);
            Vt[(d4 + 2) * 64 + (kpos ^ (2 << 3))] = tf32r(v.z);
            Vt[(d4 + 3) * 64 + (kpos ^ (3 << 3))] = tf32r(v.w);
        }
        if (tid < 64) gks[tid] = gidx[b * K_ + kc + tid];
        __syncthreads();

        // ---- S = Q K^T ----
        float s[8][4];
#pragma unroll
        for (int i = 0; i < 8; ++i)
#pragma unroll
            for (int j = 0; j < 4; ++j) s[i][j] = 0.f;

        const float* Aq0 = Qs + r0 * 64;
        const float* Aq1 = Qs + (r0 + 8) * 64;
#pragma unroll
        for (int ks = 0; ks < 8; ++ks) {
            const int col = ((8 * ks) ^ xr) + 2 * t;
            unsigned a[4];
            float2 lo = *(const float2*)(Aq0 + col);
            float2 hi = *(const float2*)(Aq1 + col);
            a[0] = __float_as_uint(lo.x); a[1] = __float_as_uint(hi.x);
            a[2] = __float_as_uint(lo.y); a[3] = __float_as_uint(hi.y);
#pragma unroll
            for (int nt = 0; nt < 8; ++nt) {
                float2 bb = *(const float2*)(Kt + (nt * 8 + g) * 64 + col);
                unsigned bf[2] = { __float_as_uint(bb.x), __float_as_uint(bb.y) };
                mma_tf32(s[nt], a, bf);
            }
        }

        // ---- mask + online softmax ----
        float cm0 = -1e30f, cm1 = -1e30f;
#pragma unroll
        for (int nt = 0; nt < 8; ++nt) {
            const int k0i = gks[nt * 8 + 2 * t];
            const int k1i = gks[nt * 8 + 2 * t + 1];
            if (gq0 == k0i) s[nt][0] = -1000000000.0f;
            if (gq0 == k1i) s[nt][1] = -1000000000.0f;
            if (gq1 == k0i) s[nt][2] = -1000000000.0f;
            if (gq1 == k1i) s[nt][3] = -1000000000.0f;
            cm0 = fmaxf(cm0, fmaxf(s[nt][0], s[nt][1]));
            cm1 = fmaxf(cm1, fmaxf(s[nt][2], s[nt][3]));
        }
        cm0 = fmaxf(cm0, __shfl_xor_sync(~0u, cm0, 1));
        cm0 = fmaxf(cm0, __shfl_xor_sync(~0u, cm0, 2));
        cm1 = fmaxf(cm1, __shfl_xor_sync(~0u, cm1, 1));
        cm1 = fmaxf(cm1, __shfl_xor_sync(~0u, cm1, 2));

        const float mn0 = fmaxf(m0, cm0), mn1 = fmaxf(m1, cm1);
        const float f0 = __expf(m0 - mn0), f1 = __expf(m1 - mn1);
        m0 = mn0; m1 = mn1;

        float rs0 = 0.f, rs1 = 0.f;
#pragma unroll
        for (int nt = 0; nt < 8; ++nt) {
            s[nt][0] = __expf(s[nt][0] - mn0); rs0 += s[nt][0];
            s[nt][1] = __expf(s[nt][1] - mn0); rs0 += s[nt][1];
            s[nt][2] = __expf(s[nt][2] - mn1); rs1 += s[nt][2];
            s[nt][3] = __expf(s[nt][3] - mn1); rs1 += s[nt][3];
        }
        rs0 += __shfl_xor_sync(~0u, rs0, 1);
        rs0 += __shfl_xor_sync(~0u, rs0, 2);
        rs1 += __shfl_xor_sync(~0u, rs1, 1);
        rs1 += __shfl_xor_sync(~0u, rs1, 2);
        l0 = l0 * f0 + rs0;
        l1 = l1 * f1 + rs1;
#pragma unroll
        for (int nt = 0; nt < 8; ++nt) {
            o[nt][0] *= f0; o[nt][1] *= f0;
            o[nt][2] *= f1; o[nt][3] *= f1;
        }

        // ---- write P (own rows only -> warp-local) ----
        float* Pr0 = Ps + r0 * 64;
        float* Pr1 = Ps + (r0 + 8) * 64;
#pragma unroll
        for (int nt = 0; nt < 8; ++nt) {
            const int cb = (nt * 8) ^ xr;
            Pr0[cb + p0] = tf32r(s[nt][0]);
            Pr0[cb + p1] = tf32r(s[nt][1]);
            Pr1[cb + p0] = tf32r(s[nt][2]);
            Pr1[cb + p1] = tf32r(s[nt][3]);
        }
        __syncwarp();

        // ---- O += P V ----
#pragma unroll
        for (int ks = 0; ks < 8; ++ks) {
            const int col = ((8 * ks) ^ xr) + 2 * t;
            unsigned a[4];
            float2 lo = *(const float2*)(Pr0 + col);
            float2 hi = *(const float2*)(Pr1 + col);
            a[0] = __float_as_uint(lo.x); a[1] = __float_as_uint(hi.x);
            a[2] = __float_as_uint(lo.y); a[3] = __float_as_uint(hi.y);
#pragma unroll
            for (int dt = 0; dt < 8; ++dt) {
                float2 bb = *(const float2*)(Vt + (dt * 8 + g) * 64 + col);
                unsigned bf[2] = { __float_as_uint(bb.x), __float_as_uint(bb.y) };
                mma_tf32(o[dt], a, bf);
            }
        }
        __syncwarp();   // P reads done before next chunk's writes
    }

    // ---- normalize + store ----
    const float i0 = 1.0f / l0, i1 = 1.0f / l1;
    float* o0 = Out + (size_t)(b * S_ + q0 + r0) * D_ + h * HD_ + 2 * t;
    float* o1 = Out + (size_t)(b * S_ + q0 + r0 + 8) * D_ + h * HD_ + 2 * t;
#pragma unroll
    for (int dt = 0; dt < 8; ++dt) {
        *(float2*)(o0 + dt * 8) = make_float2(o[dt][0] * i0, o[dt][1] * i0);
        *(float2*)(o1 + dt * 8) = make_float2(o[dt][2] * i1, o[dt][3] * i1);
    }
}

// ---------------------------------------------------------------------------
// Gated residual: dst = qe ? g * go + xres : xres
// ---------------------------------------------------------------------------
__global__ void resid_kernel(const float* __restrict__ go, const float* __restrict__ xres,
                             const int* __restrict__ qe, float* __restrict__ dst, int gOff)
{
    const int i4 = blockIdx.x * blockDim.x + threadIdx.x;
    const int e   = i4 * 4;
    const int d   = e & (D_ - 1);
    const int row = e >> 10;
    const int b   = row >> 10;
    const float4 o  = *(const float4*)(go + e);
    const float4 xr = *(const float4*)(xres + e);
    float4 r;
    if (qe[row]) {
        const float4 g = *(const float4*)(g_mod + b * MODD_ + gOff + d);
        r.x = g.x * o.x + xr.x; r.y = g.y * o.y + xr.y;
        r.z = g.z * o.z + xr.z; r.w = g.w * o.w + xr.w;
    } else {
        r = xr;
    }
    *(float4*)(dst + e) = r;
}

// ---------------------------------------------------------------------------
// Host launcher
// ---------------------------------------------------------------------------
extern "C" void kernel_launch(void* const* d_in, const int* in_sizes, int n_in,
                              void* d_out, int out_size)
{
    const float* q_x    = (const float*)d_in[0];
    const float* kv_x   = (const float*)d_in[1];
    const float* t_cond = (const float*)d_in[2];
    const float* cos_q  = (const float*)d_in[3];
    const float* sin_q  = (const float*)d_in[4];
    const float* cos_k  = (const float*)d_in[5];
    const float* sin_k  = (const float*)d_in[6];
    const int*   gidx   = (const int*)d_in[7];
    const int*   qe     = (const int*)d_in[8];
    const float* qn_w   = (const float*)d_in[9];
    const float* kvn_w  = (const float*)d_in[10];
    const float* n2_w   = (const float*)d_in[11];
    const float* Wq     = (const float*)d_in[12];
    const float* Wkv    = (const float*)d_in[13];
    const float* Wo     = (const float*)d_in[14];
    const float* W1     = (const float*)d_in[15];
    const float* b1     = (const float*)d_in[16];
    const float* W2     = (const float*)d_in[17];
    const float* b2     = (const float*)d_in[18];
    const float* adaW   = (const float*)d_in[19];
    const float* adab   = (const float*)d_in[20];

    float *p_qn, *p_kvn, *p_q, *p_kv, *p_attn, *p_o, *p_x1, *p_hn, *p_h1, *p_h2;
    cudaGetSymbolAddress((void**)&p_qn,   g_qn);
    cudaGetSymbolAddress((void**)&p_kvn,  g_kvn);
    cudaGetSymbolAddress((void**)&p_q,    g_q);
    cudaGetSymbolAddress((void**)&p_kv,   g_kv);
    cudaGetSymbolAddress((void**)&p_attn, g_attn);
    cudaGetSymbolAddress((void**)&p_o,    g_o);
    cudaGetSymbolAddress((void**)&p_x1,   g_x1);
    cudaGetSymbolAddress((void**)&p_hn,   g_hn);
    cudaGetSymbolAddress((void**)&p_h1,   g_h1);
    cudaGetSymbolAddress((void**)&p_h2,   g_h2);

    static bool attr_set = false;
    if (!attr_set) {
        cudaFuncSetAttribute(attn_mma_kernel,
                             cudaFuncAttributeMaxDynamicSharedMemorySize,
                             ATTN_SMEM_BYTES);
        attr_set = true;
    }

    const int M = B_ * S_;                   // 4096

    // 1. adaLN modulation
    mod_kernel<<<MODD_ / 256, 256>>>(t_cond, adaW, adab);

    // 2. LayerNorms (+ msa modulation for q)
    ln_kernel<<<M, 256>>>(q_x,  qn_w,  p_qn,  0, D_, 1);
    ln_kernel<<<M, 256>>>(kv_x, kvn_w, p_kvn, 0, 0,  0);

    // 3. Projections (tf32 tensor cores)
    mma_gemm<0><<<dim3(D_ / 128,      M / 128), 256>>>(p_qn,  Wq,  nullptr, p_q,  M, D_,      D_);
    mma_gemm<0><<<dim3(2 * D_ / 128,  M / 128), 256>>>(p_kvn, Wkv, nullptr, p_kv, M, 2 * D_,  D_);

    // 4. RoPE (q and k in place)
    const int nrope = B_ * 1024 * H_ * 32;   // 2M pairs
    rope_kernel<<<nrope / 256, 256>>>(p_q,  cos_q, sin_q, D_,     nrope);
    rope_kernel<<<nrope / 256, 256>>>(p_kv, cos_k, sin_k, 2 * D_, nrope);

    // 5. Attention (tensor-core flash attention)
    attn_mma_kernel<<<dim3(S_ / 128, B_ * H_), 256, ATTN_SMEM_BYTES>>>(
        p_q, p_kv, gidx, p_attn);

    // 6. Output projection + gated residual -> x_mid
    mma_gemm<0><<<dim3(D_ / 128, M / 128), 256>>>(p_attn, Wo, nullptr, p_o, M, D_, D_);
    resid_kernel<<<(M * D_ / 4) / 256, 256>>>(p_o, q_x, qe, p_x1, 2 * D_);

    // 7. MLP
    ln_kernel<<<M, 256>>>(p_x1, n2_w, p_hn, 3 * D_, 4 * D_, 1);
    mma_gemm<2><<<dim3(HID_ / 128, M / 128), 256>>>(p_hn, W1, b1, p_h1, M, HID_, D_);
    mma_gemm<1><<<dim3(D_ / 128,   M / 128), 256>>>(p_h1, W2, b2, p_h2, M, D_, HID_);

    // 8. Final gated residual -> output
    resid_kernel<<<(M * D_ / 4) / 256, 256>>>(p_h2, p_x1, qe, (float*)d_out, 5 * D_);
}